// round 8
// baseline (speedup 1.0000x reference)
#include <cuda_runtime.h>

// Conv2D 4096x4096 (*) 15x15 valid -> 4082x4082, fp32.
// R5 resubmit of R4 (infra failure, kernel unchanged):
// Packed fp32 FMA (fma.rn.f32x2, Blackwell FFMA2) halves the FFMA-class
// instruction stream, which R2/R3 showed is the invariant binder (~2.44
// FFMA/cyc/SM regardless of L1/occupancy). ky-pair row sharing retained to
// keep the LDS crossbar (~83us busy) under the new compute floor (~82us).
// RY=6 so regs (~126) fit the 128-reg cap at 2 CTAs/SM.

#define HGT 4096
#define WID 4096
#define KH  15
#define KW  15
#define OH  (HGT - KH + 1)   // 4082
#define OW  (WID - KW + 1)   // 4082

#define TW  128
#define TH  48
#define RX  4
#define RY  6
#define SW  144              // smem tile pitch in floats
#define SH  (TH + KH - 1)    // 62 rows

__device__ __forceinline__ void ffma2(unsigned long long& d,
                                      unsigned long long a,
                                      unsigned long long b) {
    asm("fma.rn.f32x2 %0, %1, %2, %0;" : "+l"(d) : "l"(a), "l"(b));
}
__device__ __forceinline__ unsigned long long pk2(float lo, float hi) {
    unsigned long long r;
    asm("mov.b64 %0, {%1, %2};" : "=l"(r) : "f"(lo), "f"(hi));
    return r;
}
__device__ __forceinline__ float2 upk(unsigned long long v) {
    float2 f;
    asm("mov.b64 {%0, %1}, %2;" : "=f"(f.x), "=f"(f.y) : "l"(v));
    return f;
}

// One (ky, output-row) contribution: 15 kx taps into 2 packed accumulators.
// A[0] covers outputs (j0,j1), A[1] covers (j2,j3).
// ev[h] = window pair at col 2h; od[h] = window pair at col 2h+1.
__device__ __forceinline__ void row_fma(unsigned long long* A,
                                        const unsigned long long* wv,
                                        const unsigned long long* ev,
                                        const unsigned long long* od) {
    #pragma unroll
    for (int h = 0; h < 8; h++) {          // kx = 2h (0,2,...,14)
        ffma2(A[0], wv[2 * h], ev[h]);
        ffma2(A[1], wv[2 * h], ev[h + 1]);
    }
    #pragma unroll
    for (int h = 0; h < 7; h++) {          // kx = 2h+1 (1,3,...,13)
        ffma2(A[0], wv[2 * h + 1], od[h]);
        ffma2(A[1], wv[2 * h + 1], od[h + 1]);
    }
}

__global__ __launch_bounds__(256, 2)
void conv2d15_kernel(const float* __restrict__ x,
                     const float* __restrict__ w,
                     const float* __restrict__ bias,
                     float* __restrict__ out) {
    __shared__ float tile[SH][SW];
    __shared__ float2 swt2[KH][16];       // splatted weights (w,w), padded

    const int tx  = threadIdx.x;          // 0..31
    const int ty  = threadIdx.y;          // 0..7
    const int tid = ty * 32 + tx;
    const int col0 = blockIdx.x * TW;
    const int row0 = blockIdx.y * TH;

    // weight splats, zero-padded to 16/row
    if (tid < KH * 16) {
        int r = tid / 16, c = tid % 16;
        float v = (c < KW) ? w[r * KW + c] : 0.f;
        swt2[r][c] = make_float2(v, v);
    }

    // ---- load input tile (SH x SW floats) with float4, zero-fill OOB ----
    const int NV4 = SW / 4;               // 36 float4 per row
    for (int idx = tid; idx < SH * NV4; idx += 256) {
        int r  = idx / NV4;
        int c4 = idx - r * NV4;
        int gr = row0 + r;
        int gc = col0 + c4 * 4;
        float4 v;
        if (gr < HGT && gc + 3 < WID) {
            v = *(const float4*)(x + (size_t)gr * WID + gc);
        } else {
            v.x = (gr < HGT && gc + 0 < WID) ? x[(size_t)gr * WID + gc + 0] : 0.f;
            v.y = (gr < HGT && gc + 1 < WID) ? x[(size_t)gr * WID + gc + 1] : 0.f;
            v.z = (gr < HGT && gc + 2 < WID) ? x[(size_t)gr * WID + gc + 2] : 0.f;
            v.w = (gr < HGT && gc + 3 < WID) ? x[(size_t)gr * WID + gc + 3] : 0.f;
        }
        *(float4*)&tile[r][c4 * 4] = v;
    }
    __syncthreads();

    unsigned long long acc2[RY][2];
    #pragma unroll
    for (int i = 0; i < RY; i++) { acc2[i][0] = 0ull; acc2[i][1] = 0ull; }

    const int txc = tx * RX;              // first output col inside tile
    const int tyr = ty * RY;              // first output row inside tile

    // ---- ky-pair loop: ky = 2*kp, 2*kp+1 share RY+1 input rows ----
    #pragma unroll 1
    for (int kp = 0; kp < KH / 2; kp++) {
        unsigned long long wa[KW], wb[KW];
        {
            const unsigned long long* wpa =
                (const unsigned long long*)&swt2[2 * kp][0];
            const unsigned long long* wpb =
                (const unsigned long long*)&swt2[2 * kp + 1][0];
            #pragma unroll
            for (int k = 0; k < KW; k++) { wa[k] = wpa[k]; wb[k] = wpb[k]; }
        }
        #pragma unroll
        for (int t = 0; t <= RY; t++) {   // RY+1 shared rows
            const int r = tyr + 2 * kp + t;
            float2 e[9];
            const float2* p = (const float2*)&tile[r][txc];
            #pragma unroll
            for (int q = 0; q < 9; q++) e[q] = p[q];
            unsigned long long ev[9], od[8];
            #pragma unroll
            for (int q = 0; q < 9; q++) ev[q] = pk2(e[q].x, e[q].y);
            #pragma unroll
            for (int q = 0; q < 8; q++) od[q] = pk2(e[q].y, e[q + 1].x);

            if (t < RY) row_fma(acc2[t],     wa, ev, od);  // ky = 2kp
            if (t > 0)  row_fma(acc2[t - 1], wb, ev, od);  // ky = 2kp+1
        }
    }

    // ---- solo ky = 14 ----
    {
        unsigned long long wa[KW];
        const unsigned long long* wpa =
            (const unsigned long long*)&swt2[KH - 1][0];
        #pragma unroll
        for (int k = 0; k < KW; k++) wa[k] = wpa[k];
        #pragma unroll
        for (int t = 0; t < RY; t++) {
            const int r = tyr + (KH - 1) + t;
            float2 e[9];
            const float2* p = (const float2*)&tile[r][txc];
            #pragma unroll
            for (int q = 0; q < 9; q++) e[q] = p[q];
            unsigned long long ev[9], od[8];
            #pragma unroll
            for (int q = 0; q < 9; q++) ev[q] = pk2(e[q].x, e[q].y);
            #pragma unroll
            for (int q = 0; q < 8; q++) od[q] = pk2(e[q].y, e[q + 1].x);
            row_fma(acc2[t], wa, ev, od);
        }
    }

    // ---- store with bias ----
    const float b = bias[0];
    const int ocol = col0 + txc;
    #pragma unroll
    for (int i = 0; i < RY; i++) {
        const int orow = row0 + tyr + i;
        if (orow < OH) {
            float2 lo = upk(acc2[i][0]);
            float2 hi = upk(acc2[i][1]);
            float v0 = lo.x + b, v1 = lo.y + b, v2 = hi.x + b, v3 = hi.y + b;
            float* o = out + (size_t)orow * OW + ocol;
            if (ocol + 3 < OW) {
                // row pitch 4082 floats: (even row base + even col)*4 is 8B
                // aligned -> two STG.64
                *(float2*)(o)     = make_float2(v0, v1);
                *(float2*)(o + 2) = make_float2(v2, v3);
            } else {
                if (ocol + 0 < OW) o[0] = v0;
                if (ocol + 1 < OW) o[1] = v1;
                if (ocol + 2 < OW) o[2] = v2;
                if (ocol + 3 < OW) o[3] = v3;
            }
        }
    }
}

extern "C" void kernel_launch(void* const* d_in, const int* in_sizes, int n_in,
                              void* d_out, int out_size) {
    const float* x    = (const float*)d_in[0];
    const float* w    = (const float*)d_in[1];
    const float* bias = (const float*)d_in[2];
    float* out        = (float*)d_out;

    dim3 block(32, 8, 1);
    dim3 grid((OW + TW - 1) / TW, (OH + TH - 1) / TH, 1);  // (32, 86)
    conv2d15_kernel<<<grid, block>>>(x, w, bias, out);
}

// round 12
// speedup vs baseline: 1.3079x; 1.3079x over previous
#include <cuda_runtime.h>

// Conv2D 4096x4096 (*) 15x15 valid -> 4082x4082, fp32.
// R11 resubmit of R9 (infra failure, kernel unchanged):
// Scalar FFMA (FFMA2 proven throughput-neutral on B300 and its packing
// MOVs regressed to 203us). Combine the two levers that individually were
// neutral: (a) ky-pair row sharing halves LDS traffic (L1 56%), (b) 3 CTAs/SM
// (24 warps) to cover the 29-cyc LDS latency that capped issue at ~68-73%.
// RY=6 keeps regs ~84 <= 85 so occupancy 3 holds.

#define HGT 4096
#define WID 4096
#define KH  15
#define KW  15
#define OH  (HGT - KH + 1)   // 4082
#define OW  (WID - KW + 1)   // 4082

#define TW  128
#define TH  48
#define RX  4
#define RY  6
#define SW  144              // smem tile pitch in floats
#define SH  (TH + KH - 1)    // 62 rows

__global__ __launch_bounds__(256, 3)
void conv2d15_kernel(const float* __restrict__ x,
                     const float* __restrict__ w,
                     const float* __restrict__ bias,
                     float* __restrict__ out) {
    __shared__ float tile[SH][SW];
    __shared__ float swt[KH][16];         // weight rows padded to 16 floats

    const int tx  = threadIdx.x;          // 0..31
    const int ty  = threadIdx.y;          // 0..7
    const int tid = ty * 32 + tx;
    const int col0 = blockIdx.x * TW;
    const int row0 = blockIdx.y * TH;

    if (tid < KH * 16) {
        int r = tid / 16, c = tid % 16;
        swt[r][c] = (c < KW) ? w[r * KW + c] : 0.f;
    }

    // ---- load input tile (SH x SW floats) with float4, zero-fill OOB ----
    const int NV4 = SW / 4;               // 36 float4 per row
    for (int idx = tid; idx < SH * NV4; idx += 256) {
        int r  = idx / NV4;
        int c4 = idx - r * NV4;
        int gr = row0 + r;
        int gc = col0 + c4 * 4;
        float4 v;
        if (gr < HGT && gc + 3 < WID) {
            v = *(const float4*)(x + (size_t)gr * WID + gc);
        } else {
            v.x = (gr < HGT && gc + 0 < WID) ? x[(size_t)gr * WID + gc + 0] : 0.f;
            v.y = (gr < HGT && gc + 1 < WID) ? x[(size_t)gr * WID + gc + 1] : 0.f;
            v.z = (gr < HGT && gc + 2 < WID) ? x[(size_t)gr * WID + gc + 2] : 0.f;
            v.w = (gr < HGT && gc + 3 < WID) ? x[(size_t)gr * WID + gc + 3] : 0.f;
        }
        *(float4*)&tile[r][c4 * 4] = v;
    }
    __syncthreads();

    float acc[RY][RX];
    #pragma unroll
    for (int i = 0; i < RY; i++)
        #pragma unroll
        for (int j = 0; j < RX; j++)
            acc[i][j] = 0.f;

    const int txc = tx * RX;              // first output col inside tile (16B aligned)
    const int tyr = ty * RY;              // first output row inside tile

    // ---- ky-pair loop: ky = 2*kp, 2*kp+1 share RY+1 input rows ----
    #pragma unroll 1
    for (int kp = 0; kp < KH / 2; kp++) { // 7 pairs (ky 0..13)
        float wa[KW], wb[KW];
        {
            const float4* pa = (const float4*)&swt[2 * kp][0];
            const float4* pb = (const float4*)&swt[2 * kp + 1][0];
            #pragma unroll
            for (int q = 0; q < 4; q++) {
                float4 va = pa[q], vb = pb[q];
                if (q * 4 + 0 < KW) { wa[q*4+0] = va.x; wb[q*4+0] = vb.x; }
                if (q * 4 + 1 < KW) { wa[q*4+1] = va.y; wb[q*4+1] = vb.y; }
                if (q * 4 + 2 < KW) { wa[q*4+2] = va.z; wb[q*4+2] = vb.z; }
                if (q * 4 + 3 < KW) { wa[q*4+3] = va.w; wb[q*4+3] = vb.w; }
            }
        }
        #pragma unroll
        for (int t = 0; t <= RY; t++) {   // RY+1 shared rows
            const int r = tyr + 2 * kp + t;
            float win[20];
            const float4* p = (const float4*)&tile[r][txc];
            #pragma unroll
            for (int q = 0; q < 5; q++) {
                float4 v = p[q];
                win[q*4+0]=v.x; win[q*4+1]=v.y; win[q*4+2]=v.z; win[q*4+3]=v.w;
            }
            if (t < RY) {        // (ky=2kp, i=t)
                #pragma unroll
                for (int kx = 0; kx < KW; kx++) {
                    const float wv = wa[kx];
                    #pragma unroll
                    for (int j = 0; j < RX; j++)
                        acc[t][j] = fmaf(wv, win[kx + j], acc[t][j]);
                }
            }
            if (t > 0) {         // (ky=2kp+1, i=t-1)
                #pragma unroll
                for (int kx = 0; kx < KW; kx++) {
                    const float wv = wb[kx];
                    #pragma unroll
                    for (int j = 0; j < RX; j++)
                        acc[t - 1][j] = fmaf(wv, win[kx + j], acc[t - 1][j]);
                }
            }
        }
    }

    // ---- solo ky = 14 ----
    {
        float wa[KW];
        const float4* pa = (const float4*)&swt[KH - 1][0];
        #pragma unroll
        for (int q = 0; q < 4; q++) {
            float4 va = pa[q];
            if (q * 4 + 0 < KW) wa[q*4+0] = va.x;
            if (q * 4 + 1 < KW) wa[q*4+1] = va.y;
            if (q * 4 + 2 < KW) wa[q*4+2] = va.z;
            if (q * 4 + 3 < KW) wa[q*4+3] = va.w;
        }
        #pragma unroll
        for (int t = 0; t < RY; t++) {
            const int r = tyr + (KH - 1) + t;
            float win[20];
            const float4* p = (const float4*)&tile[r][txc];
            #pragma unroll
            for (int q = 0; q < 5; q++) {
                float4 v = p[q];
                win[q*4+0]=v.x; win[q*4+1]=v.y; win[q*4+2]=v.z; win[q*4+3]=v.w;
            }
            #pragma unroll
            for (int kx = 0; kx < KW; kx++) {
                const float wv = wa[kx];
                #pragma unroll
                for (int j = 0; j < RX; j++)
                    acc[t][j] = fmaf(wv, win[kx + j], acc[t][j]);
            }
        }
    }

    // ---- store with bias ----
    const float b = bias[0];
    const int ocol = col0 + txc;
    #pragma unroll
    for (int i = 0; i < RY; i++) {
        const int orow = row0 + tyr + i;
        if (orow < OH) {
            float v0 = acc[i][0] + b, v1 = acc[i][1] + b;
            float v2 = acc[i][2] + b, v3 = acc[i][3] + b;
            float* o = out + (size_t)orow * OW + ocol;
            if (ocol + 3 < OW) {
                *(float2*)(o)     = make_float2(v0, v1);
                *(float2*)(o + 2) = make_float2(v2, v3);
            } else {
                if (ocol + 0 < OW) o[0] = v0;
                if (ocol + 1 < OW) o[1] = v1;
                if (ocol + 2 < OW) o[2] = v2;
                if (ocol + 3 < OW) o[3] = v3;
            }
        }
    }
}

extern "C" void kernel_launch(void* const* d_in, const int* in_sizes, int n_in,
                              void* d_out, int out_size) {
    const float* x    = (const float*)d_in[0];
    const float* w    = (const float*)d_in[1];
    const float* bias = (const float*)d_in[2];
    float* out        = (float*)d_out;

    dim3 block(32, 8, 1);
    dim3 grid((OW + TW - 1) / TW, (OH + TH - 1) / TH, 1);  // (32, 86)
    conv2d15_kernel<<<grid, block>>>(x, w, bias, out);
}

// round 16
// speedup vs baseline: 1.4523x; 1.1105x over previous
#include <cuda_runtime.h>

// Conv2D 4096x4096 (*) 15x15 valid -> 4082x4082, fp32.
// R15: tcgen05 is unavailable (harness PTX targets sm_103 without the 'a'
// feature set -> all tcgen05/TMEM instructions rejected). Scalar path it is.
// Change vs R12 (155us): weights move to __constant__ (staged by an async D2D
// memcpy-to-symbol in kernel_launch; graph-capturable). ptxas reads them via
// the uniform path (LDCU -> UR operands in FFMA), freeing the 30 GPRs that
// cached wa/wb. Regs ~72 -> ~60, enabling __launch_bounds__(256,4) = 32
// warps/SM to cover LDS latency (R12: issue 76.5%, fma 63.5% at 24 warps).

#define HGT 4096
#define WID 4096
#define KH  15
#define KW  15
#define OH  (HGT - KH + 1)   // 4082
#define OW  (WID - KW + 1)   // 4082

#define TW  128
#define TH  48
#define RX  4
#define RY  6
#define SW  144              // smem tile pitch in floats
#define SH  (TH + KH - 1)    // 62 rows

__constant__ float CW[KH * KW];   // 225 weights

__global__ __launch_bounds__(256, 4)
void conv2d15_kernel(const float* __restrict__ x,
                     const float* __restrict__ bias,
                     float* __restrict__ out) {
    __shared__ float tile[SH][SW];

    const int tx  = threadIdx.x;          // 0..31
    const int ty  = threadIdx.y;          // 0..7
    const int tid = ty * 32 + tx;
    const int col0 = blockIdx.x * TW;
    const int row0 = blockIdx.y * TH;

    // ---- load input tile (SH x SW floats) with float4, zero-fill OOB ----
    const int NV4 = SW / 4;               // 36 float4 per row
    for (int idx = tid; idx < SH * NV4; idx += 256) {
        int r  = idx / NV4;
        int c4 = idx - r * NV4;
        int gr = row0 + r;
        int gc = col0 + c4 * 4;
        float4 v;
        if (gr < HGT && gc + 3 < WID) {
            v = *(const float4*)(x + (size_t)gr * WID + gc);
        } else {
            v.x = (gr < HGT && gc + 0 < WID) ? x[(size_t)gr * WID + gc + 0] : 0.f;
            v.y = (gr < HGT && gc + 1 < WID) ? x[(size_t)gr * WID + gc + 1] : 0.f;
            v.z = (gr < HGT && gc + 2 < WID) ? x[(size_t)gr * WID + gc + 2] : 0.f;
            v.w = (gr < HGT && gc + 3 < WID) ? x[(size_t)gr * WID + gc + 3] : 0.f;
        }
        *(float4*)&tile[r][c4 * 4] = v;
    }
    __syncthreads();

    float acc[RY][RX];
    #pragma unroll
    for (int i = 0; i < RY; i++)
        #pragma unroll
        for (int j = 0; j < RX; j++)
            acc[i][j] = 0.f;

    const int txc = tx * RX;              // first output col inside tile (16B aligned)
    const int tyr = ty * RY;              // first output row inside tile

    // ---- ky-pair loop: ky = 2*kp, 2*kp+1 share RY+1 input rows ----
    // Weights come straight from __constant__: uniform LDCU -> UR operands,
    // hoisted per kp by ptxas; no GPR or LDS cost.
    #pragma unroll 1
    for (int kp = 0; kp < KH / 2; kp++) { // 7 pairs (ky 0..13)
        const int wbase = kp * (2 * KW);  // CW offset of row 2kp
        #pragma unroll
        for (int t = 0; t <= RY; t++) {   // RY+1 shared rows
            const int r = tyr + 2 * kp + t;
            float win[20];
            const float4* p = (const float4*)&tile[r][txc];
            #pragma unroll
            for (int q = 0; q < 5; q++) {
                float4 v = p[q];
                win[q*4+0]=v.x; win[q*4+1]=v.y; win[q*4+2]=v.z; win[q*4+3]=v.w;
            }
            if (t < RY) {        // (ky=2kp, i=t)
                #pragma unroll
                for (int kx = 0; kx < KW; kx++) {
                    const float wv = CW[wbase + kx];
                    #pragma unroll
                    for (int j = 0; j < RX; j++)
                        acc[t][j] = fmaf(wv, win[kx + j], acc[t][j]);
                }
            }
            if (t > 0) {         // (ky=2kp+1, i=t-1)
                #pragma unroll
                for (int kx = 0; kx < KW; kx++) {
                    const float wv = CW[wbase + KW + kx];
                    #pragma unroll
                    for (int j = 0; j < RX; j++)
                        acc[t - 1][j] = fmaf(wv, win[kx + j], acc[t - 1][j]);
                }
            }
        }
    }

    // ---- solo ky = 14 ----
    {
        #pragma unroll
        for (int t = 0; t < RY; t++) {
            const int r = tyr + (KH - 1) + t;
            float win[20];
            const float4* p = (const float4*)&tile[r][txc];
            #pragma unroll
            for (int q = 0; q < 5; q++) {
                float4 v = p[q];
                win[q*4+0]=v.x; win[q*4+1]=v.y; win[q*4+2]=v.z; win[q*4+3]=v.w;
            }
            #pragma unroll
            for (int kx = 0; kx < KW; kx++) {
                const float wv = CW[(KH - 1) * KW + kx];
                #pragma unroll
                for (int j = 0; j < RX; j++)
                    acc[t][j] = fmaf(wv, win[kx + j], acc[t][j]);
            }
        }
    }

    // ---- store with bias ----
    const float b = bias[0];
    const int ocol = col0 + txc;
    #pragma unroll
    for (int i = 0; i < RY; i++) {
        const int orow = row0 + tyr + i;
        if (orow < OH) {
            float v0 = acc[i][0] + b, v1 = acc[i][1] + b;
            float v2 = acc[i][2] + b, v3 = acc[i][3] + b;
            float* o = out + (size_t)orow * OW + ocol;
            if (ocol + 3 < OW) {
                *(float2*)(o)     = make_float2(v0, v1);
                *(float2*)(o + 2) = make_float2(v2, v3);
            } else {
                if (ocol + 0 < OW) o[0] = v0;
                if (ocol + 1 < OW) o[1] = v1;
                if (ocol + 2 < OW) o[2] = v2;
                if (ocol + 3 < OW) o[3] = v3;
            }
        }
    }
}

extern "C" void kernel_launch(void* const* d_in, const int* in_sizes, int n_in,
                              void* d_out, int out_size) {
    const float* x    = (const float*)d_in[0];
    const float* w    = (const float*)d_in[1];
    const float* bias = (const float*)d_in[2];
    float* out        = (float*)d_out;

    // Stage weights into __constant__ (device-to-device, async: capturable).
    cudaMemcpyToSymbolAsync(CW, w, KH * KW * sizeof(float), 0,
                            cudaMemcpyDeviceToDevice, 0);

    dim3 block(32, 8, 1);
    dim3 grid((OW + TW - 1) / TW, (OH + TH - 1) / TH, 1);  // (32, 86)
    conv2d15_kernel<<<grid, block>>>(x, bias, out);
}